// round 2
// baseline (speedup 1.0000x reference)
#include <cuda_runtime.h>
#include <cstddef>

// Problem constants
#define A_ATOMS 2048
#define DEPTH   64
#define FILT    12
#define KTOT    (A_ATOMS * FILT)   // 24576
#define MTOT    A_ATOMS            // 2048
#define NTOT    DEPTH              // 64
#define MN      (MTOT * NTOT)      // 131072

// GEMM tiling
#define BM 128
#define BN 64
#define BK 16
#define SPLITS 24
#define KC (KTOT / SPLITS)         // 1024

// -------- scratch (static device allocations; no cudaMalloc allowed) --------
__device__ float g_W[KTOT * NTOT];            // 6.29 MB   W[(n*F+f)*64 + o]
__device__ float g_part[SPLITS * MN];         // 12.6 MB   split-K partials
__device__ float g_h[MN];                     // activation buffer 1
__device__ float g_h2[MN];                    // activation buffer 2
__device__ float g_BC[2 * MN];                // bond contribution per filter set

// ---------------------------------------------------------------------------
// BC[l][a][o] = sum_{f,j} bond[a,f,j] * filters_l[o,f,64+j]
// ---------------------------------------------------------------------------
__global__ __launch_bounds__(64) void bc_kernel(const float* __restrict__ bond,
                                                const float* __restrict__ f0,
                                                const float* __restrict__ f1)
{
    int a = blockIdx.x;
    int o = threadIdx.x;  // 0..63
    __shared__ float bs[24];
    if (o < 24) bs[o] = bond[a * 24 + o];
    __syncthreads();
    float acc0 = 0.f, acc1 = 0.f;
#pragma unroll
    for (int f = 0; f < FILT; f++) {
#pragma unroll
        for (int j = 0; j < 2; j++) {
            float b = bs[f * 2 + j];
            acc0 += b * f0[o * (FILT * 66) + f * 66 + 64 + j];
            acc1 += b * f1[o * (FILT * 66) + f * 66 + 64 + j];
        }
    }
    g_BC[a * 64 + o]      = acc0;
    g_BC[MN + a * 64 + o] = acc1;
}

// ---------------------------------------------------------------------------
// W[n,f,o] = sum_d z[n,d] * filt[o,f,d]
// grid: (32 n-chunks of 64, 12 f).  256 threads, 4x4 microtile over 64n x 64o.
// ---------------------------------------------------------------------------
__global__ __launch_bounds__(256) void w_kernel(int z_sel,
                                                const float* __restrict__ x,
                                                const float* __restrict__ filt)
{
    const float* z = (z_sel == 0) ? x : (z_sel == 1 ? g_h : g_h2);
    __shared__ float Zs[64][65];   // [d][n_local]
    __shared__ float Fs[64][65];   // [d][o]
    const int f   = blockIdx.y;
    const int n0  = blockIdx.x * 64;
    const int tid = threadIdx.x;

    // load z rows (64 x 64), transpose into Zs[d][n]
#pragma unroll
    for (int it = 0; it < 4; it++) {
        int n = (tid >> 4) + it * 16;
        int d = (tid & 15) << 2;
        float4 v = *(const float4*)(z + (size_t)(n0 + n) * 64 + d);
        Zs[d + 0][n] = v.x; Zs[d + 1][n] = v.y;
        Zs[d + 2][n] = v.z; Zs[d + 3][n] = v.w;
    }
    // load filt[o][f][0:64], transpose into Fs[d][o]  (float2: offsets all even)
#pragma unroll
    for (int it = 0; it < 8; it++) {
        int idx = tid + it * 256;          // 0..2047
        int o   = idx >> 5;                // /32
        int d2  = (idx & 31) << 1;
        float2 v = *(const float2*)(filt + (size_t)o * (FILT * 66) + f * 66 + d2);
        Fs[d2][o]     = v.x;
        Fs[d2 + 1][o] = v.y;
    }
    __syncthreads();

    const int ty = tid >> 4, tx = tid & 15;
    float acc[4][4] = {};
#pragma unroll 8
    for (int d = 0; d < 64; d++) {
        float zv[4], fv[4];
#pragma unroll
        for (int i = 0; i < 4; i++) zv[i] = Zs[d][ty * 4 + i];
#pragma unroll
        for (int j = 0; j < 4; j++) fv[j] = Fs[d][tx * 4 + j];
#pragma unroll
        for (int i = 0; i < 4; i++)
#pragma unroll
            for (int j = 0; j < 4; j++)
                acc[i][j] = fmaf(zv[i], fv[j], acc[i][j]);
    }
#pragma unroll
    for (int i = 0; i < 4; i++) {
        int n = n0 + ty * 4 + i;
        float4 v = make_float4(acc[i][0], acc[i][1], acc[i][2], acc[i][3]);
        *(float4*)(g_W + ((size_t)n * FILT + f) * 64 + tx * 4) = v;
    }
}

// ---------------------------------------------------------------------------
// Big GEMM: part[split][m][n] = sum_{k in chunk} conn[m][k] * W[k][n]
// A = conn (2048 x 24576 row-major, contiguous). B = g_W (24576 x 64).
// grid: (16 m-tiles, SPLITS k-splits), 256 threads, 8x4 microtile.
// ---------------------------------------------------------------------------
__global__ __launch_bounds__(256) void gemm_kernel(const float* __restrict__ Ag)
{
    __shared__ float As[BK][BM];
    __shared__ float Bs[BK][BN];
    const int tid = threadIdx.x;
    const int m0  = blockIdx.x * BM;
    const int k0  = blockIdx.y * KC;

    const int a_row = tid >> 2;          // 0..63 (two rows: +0, +64)
    const int a_k4  = (tid & 3) << 2;    // 0,4,8,12
    const int b_row = tid >> 4;          // 0..15
    const int b_col = (tid & 15) << 2;

    const int ty = tid >> 4;             // 0..15 -> m group (8 rows)
    const int tx = tid & 15;             // 0..15 -> n group (4 cols)

    const float* Ap = Ag + (size_t)m0 * KTOT + k0;
    const float* Bp = g_W + (size_t)k0 * NTOT;

    // prefetch stage 0
    float4 pa0 = *(const float4*)(Ap + (size_t)a_row * KTOT + a_k4);
    float4 pa1 = *(const float4*)(Ap + (size_t)(a_row + 64) * KTOT + a_k4);
    float4 pb  = *(const float4*)(Bp + (size_t)b_row * NTOT + b_col);

    float acc[8][4] = {};

    for (int ks = 0; ks < KC; ks += BK) {
        As[a_k4 + 0][a_row]      = pa0.x;
        As[a_k4 + 1][a_row]      = pa0.y;
        As[a_k4 + 2][a_row]      = pa0.z;
        As[a_k4 + 3][a_row]      = pa0.w;
        As[a_k4 + 0][a_row + 64] = pa1.x;
        As[a_k4 + 1][a_row + 64] = pa1.y;
        As[a_k4 + 2][a_row + 64] = pa1.z;
        As[a_k4 + 3][a_row + 64] = pa1.w;
        *(float4*)&Bs[b_row][b_col] = pb;
        __syncthreads();

        if (ks + BK < KC) {
            pa0 = *(const float4*)(Ap + (size_t)a_row * KTOT + (ks + BK) + a_k4);
            pa1 = *(const float4*)(Ap + (size_t)(a_row + 64) * KTOT + (ks + BK) + a_k4);
            pb  = *(const float4*)(Bp + (size_t)(ks + BK + b_row) * NTOT + b_col);
        }

#pragma unroll
        for (int kk = 0; kk < BK; kk++) {
            float4 a0 = *(const float4*)&As[kk][ty * 8];
            float4 a1 = *(const float4*)&As[kk][ty * 8 + 4];
            float4 bv = *(const float4*)&Bs[kk][tx * 4];
            float am[8] = {a0.x, a0.y, a0.z, a0.w, a1.x, a1.y, a1.z, a1.w};
            float bn[4] = {bv.x, bv.y, bv.z, bv.w};
#pragma unroll
            for (int i = 0; i < 8; i++)
#pragma unroll
                for (int j = 0; j < 4; j++)
                    acc[i][j] = fmaf(am[i], bn[j], acc[i][j]);
        }
        __syncthreads();
    }

    float* P = g_part + ((size_t)blockIdx.y * MTOT + m0) * NTOT;
#pragma unroll
    for (int i = 0; i < 8; i++) {
        int m = ty * 8 + i;
        float4 v = make_float4(acc[i][0], acc[i][1], acc[i][2], acc[i][3]);
        *(float4*)(P + (size_t)m * NTOT + tx * 4) = v;
    }
}

// ---------------------------------------------------------------------------
// reduce split-K partials + BC (+ residual) + ReLU
// dst_sel: 1 -> g_h, 2 -> g_h2, else ext_out
// ---------------------------------------------------------------------------
__global__ __launch_bounds__(256) void epi_kernel(int bc_idx,
                                                  const float* __restrict__ resid,
                                                  int dst_sel,
                                                  float* __restrict__ ext_out,
                                                  int add_resid)
{
    int i = blockIdx.x * blockDim.x + threadIdx.x;  // < 131072
    float s = 0.f;
#pragma unroll
    for (int sp = 0; sp < SPLITS; sp++)
        s += g_part[(size_t)sp * MN + i];
    s += g_BC[(size_t)bc_idx * MN + i];
    if (add_resid) s += resid[i];
    s = fmaxf(s, 0.f);
    float* dst = (dst_sel == 1) ? g_h : (dst_sel == 2 ? g_h2 : ext_out);
    dst[i] = s;
}

// ---------------------------------------------------------------------------
extern "C" void kernel_launch(void* const* d_in, const int* in_sizes, int n_in,
                              void* d_out, int out_size)
{
    const float* x    = (const float*)d_in[0];  // (2048, 64)
    const float* conn = (const float*)d_in[1];  // (2048, 2048, 12)
    const float* bond = (const float*)d_in[2];  // (2048, 12, 2)
    const float* f0   = (const float*)d_in[3];  // (64, 12, 66)
    const float* f1   = (const float*)d_in[4];  // (64, 12, 66)
    float* out = (float*)d_out;

    bc_kernel<<<A_ATOMS, 64>>>(bond, f0, f1);

    dim3 wg(32, FILT);
    dim3 gg(MTOT / BM, SPLITS);

    // layer 0, conv 1:  h = relu(conv(x, f0))          -> g_h
    w_kernel<<<wg, 256>>>(0, x, f0);
    gemm_kernel<<<gg, 256>>>(conn);
    epi_kernel<<<MN / 256, 256>>>(0, x, 1, out, 0);

    // layer 0, conv 2:  out0 = relu(conv(h, f0) + x)   -> g_h2
    w_kernel<<<wg, 256>>>(1, x, f0);
    gemm_kernel<<<gg, 256>>>(conn);
    epi_kernel<<<MN / 256, 256>>>(0, x, 2, out, 1);

    // layer 1, conv 1:  h = relu(conv(out0, f1))       -> g_h
    w_kernel<<<wg, 256>>>(2, x, f1);
    gemm_kernel<<<gg, 256>>>(conn);
    epi_kernel<<<MN / 256, 256>>>(1, x, 1, out, 0);

    // layer 1, conv 2:  final = relu(conv(h, f1) + x)  -> d_out
    w_kernel<<<wg, 256>>>(1, x, f1);
    gemm_kernel<<<gg, 256>>>(conn);
    epi_kernel<<<MN / 256, 256>>>(1, x, 0, out, 1);
}

// round 5
// speedup vs baseline: 1.0864x; 1.0864x over previous
#include <cuda_runtime.h>
#include <cstdint>
#include <cstddef>

// ---------------- problem constants ----------------
#define A_ATOMS 2048
#define DEPTH   64
#define FILT    12
#define KTOT    24576          // A_ATOMS * FILT
#define MN      131072         // A_ATOMS * DEPTH

// ---------------- GEMM config ----------------
#define BM      128
#define BN      64
#define BK      32             // floats of K per stage
#define NSPLIT  9
#define STAGES  4

#define LDK     36             // padded row length (floats) -> 144 B
#define A_STAGE_BYTES (BM * LDK * 4)        // 18432
#define B_STAGE_BYTES (BN * LDK * 4)        // 9216
#define STAGE_BYTES   (A_STAGE_BYTES + B_STAGE_BYTES)  // 27648
#define SMEM_DYN      (STAGES * STAGE_BYTES)           // 110592

// ---------------- static scratch ----------------
__device__ float g_Wt[64 * KTOT];       // W^T [o][k], RN tf32-rounded
__device__ float g_part[NSPLIT * MN];   // split-K partials
__device__ float g_h[MN];               // activation buffer
__device__ float g_BC[2 * MN];          // bond contributions

// ---------------------------------------------------------------------------
// BC[l][a][o] = sum_{f,j} bond[a,f,j] * filters_l[o,f,64+j]
// ---------------------------------------------------------------------------
__global__ __launch_bounds__(64) void bc_kernel(const float* __restrict__ bond,
                                                const float* __restrict__ f0,
                                                const float* __restrict__ f1)
{
    int a = blockIdx.x;
    int o = threadIdx.x;
    __shared__ float bs[24];
    if (o < 24) bs[o] = bond[a * 24 + o];
    __syncthreads();
    float acc0 = 0.f, acc1 = 0.f;
#pragma unroll
    for (int f = 0; f < FILT; f++)
#pragma unroll
        for (int j = 0; j < 2; j++) {
            float b = bs[f * 2 + j];
            acc0 += b * f0[o * 792 + f * 66 + 64 + j];
            acc1 += b * f1[o * 792 + f * 66 + 64 + j];
        }
    g_BC[a * 64 + o]      = acc0;
    g_BC[MN + a * 64 + o] = acc1;
}

// ---------------------------------------------------------------------------
// W^T[o][n*12+f] = round_rn_tf32( sum_d z[n,d] * filt[o,f,d] )
// ---------------------------------------------------------------------------
__global__ __launch_bounds__(256) void w2_kernel(int zsel,
                                                 const float* __restrict__ x,
                                                 const float* __restrict__ filt)
{
    const float* z = zsel ? g_h : x;
    __shared__ float act[8][64];
    __shared__ float fs[64][65];
    __shared__ float outp[64][96];
    const int n0  = blockIdx.x * 8;
    const int tid = threadIdx.x;

    if (tid < 128) {
        int r = tid >> 4, d = (tid & 15) * 4;
        *(float4*)&act[r][d] = *(const float4*)(z + (size_t)(n0 + r) * 64 + d);
    }

    const int ol = tid & 31;
    const int nl = tid >> 5;
    float acc[12][2];

#pragma unroll 1
    for (int f = 0; f < 12; f++) {
        __syncthreads();
        {
            int o  = tid >> 2;
            int d0 = (tid & 3) * 16;
#pragma unroll
            for (int c = 0; c < 8; c++) {
                float2 v = *(const float2*)(filt + (size_t)o * 792 + f * 66 + d0 + c * 2);
                fs[o][d0 + c * 2]     = v.x;
                fs[o][d0 + c * 2 + 1] = v.y;
            }
        }
        __syncthreads();
        float a0 = 0.f, a1 = 0.f;
#pragma unroll 16
        for (int d = 0; d < 64; d++) {
            float av = act[nl][d];
            a0 = fmaf(av, fs[ol * 2][d], a0);
            a1 = fmaf(av, fs[ol * 2 + 1][d], a1);
        }
        acc[f][0] = a0;
        acc[f][1] = a1;
    }

    __syncthreads();
#pragma unroll
    for (int f = 0; f < 12; f++) {
        outp[ol * 2][nl * 12 + f]     = acc[f][0];
        outp[ol * 2 + 1][nl * 12 + f] = acc[f][1];
    }
    __syncthreads();

#pragma unroll
    for (int t = 0; t < 24; t++) {
        int idx = tid + t * 256;
        int row = idx / 96, col = idx % 96;
        float v = outp[row][col];
        uint32_t u;
        asm("cvt.rna.tf32.f32 %0, %1;" : "=r"(u) : "f"(v));
        g_Wt[(size_t)row * KTOT + n0 * 12 + col] = __uint_as_float(u);
    }
}

// ---------------------------------------------------------------------------
// Big GEMM, mma.sync tf32 with 2-term A split (A_hi exact-tf32 + A_lo):
//   part[sp][m][o] = sum_{k in split} conn[m][k] * Wt[o][k]
// grid (16 m-tiles, 9 k-splits), 256 threads (8 warps: 4M x 2N, 32x32 each).
// ---------------------------------------------------------------------------
__global__ __launch_bounds__(256, 1) void gemm_mma(const float* __restrict__ Ag)
{
    extern __shared__ __align__(128) char smem[];

    const int tid  = threadIdx.x;
    const int wid  = tid >> 5;
    const int lane = tid & 31;
    const int wm   = wid & 3;
    const int wn   = wid >> 2;
    const int lr   = lane >> 2;
    const int lc   = lane & 3;

    const int sp   = blockIdx.y;
    const int kbeg = sp * 85 + (sp < 3 ? sp : 3);     // in BK units
    const int kcnt = 85 + (sp < 3 ? 1 : 0);
    const int m0   = blockIdx.x * BM;

    const float* Abase = Ag + (size_t)m0 * KTOT + (size_t)kbeg * BK;
    const float* Bbase = g_Wt + (size_t)kbeg * BK;

    const int a_row = tid >> 1;
    const int a_c0  = (tid & 1) * 4;
    const int b_row = tid >> 2;
    const int b_c0  = (tid & 3) * 2;

    auto load_stage = [&](int st, int j) {
        char* as = smem + st * STAGE_BYTES;
        char* bs = as + A_STAGE_BYTES;
        const char* ga = (const char*)(Abase + (size_t)a_row * KTOT + (size_t)j * BK);
        uint32_t da;
        asm("{ .reg .u64 t; cvta.to.shared.u64 t, %1; cvt.u32.u64 %0, t; }"
            : "=r"(da) : "l"(as + a_row * (LDK * 4)));
#pragma unroll
        for (int c = 0; c < 4; c++)
            asm volatile("cp.async.cg.shared.global [%0], [%1], 16;"
                         :: "r"(da + (a_c0 + c) * 16), "l"(ga + (a_c0 + c) * 16) : "memory");
        const char* gb = (const char*)(Bbase + (size_t)b_row * KTOT + (size_t)j * BK);
        uint32_t db;
        asm("{ .reg .u64 t; cvta.to.shared.u64 t, %1; cvt.u32.u64 %0, t; }"
            : "=r"(db) : "l"(bs + b_row * (LDK * 4)));
#pragma unroll
        for (int c = 0; c < 2; c++)
            asm volatile("cp.async.cg.shared.global [%0], [%1], 16;"
                         :: "r"(db + (b_c0 + c) * 16), "l"(gb + (b_c0 + c) * 16) : "memory");
        asm volatile("cp.async.commit_group;" ::: "memory");
    };

    float acc[2][4][4];
#pragma unroll
    for (int mi = 0; mi < 2; mi++)
#pragma unroll
        for (int ni = 0; ni < 4; ni++)
#pragma unroll
            for (int r = 0; r < 4; r++) acc[mi][ni][r] = 0.f;

    for (int j = 0; j < STAGES - 1; j++) load_stage(j, j);

    for (int i = 0; i < kcnt; i++) {
        const int s = i & (STAGES - 1);
        asm volatile("cp.async.wait_group %0;" :: "n"(STAGES - 2) : "memory");
        __syncthreads();

        const int j = i + STAGES - 1;
        if (j < kcnt) load_stage(j & (STAGES - 1), j);
        else asm volatile("cp.async.commit_group;" ::: "memory");

        const float* As = (const float*)(smem + s * STAGE_BYTES);
        const float* Bs = (const float*)(smem + s * STAGE_BYTES + A_STAGE_BYTES);

#pragma unroll
        for (int ks = 0; ks < 4; ks++) {
            const int k0 = ks * 8 + lc;
            float af[2][4];
            uint32_t a_hi[2][4], a_lo[2][4], b[4][2];
#pragma unroll
            for (int mi = 0; mi < 2; mi++) {
                const int rbase = (wm * 32 + mi * 16 + lr) * LDK;
                af[mi][0] = As[rbase + k0];
                af[mi][1] = As[rbase + 8 * LDK + k0];
                af[mi][2] = As[rbase + k0 + 4];
                af[mi][3] = As[rbase + 8 * LDK + k0 + 4];
#pragma unroll
                for (int r = 0; r < 4; r++) {
                    uint32_t hi;
                    asm("cvt.rna.tf32.f32 %0, %1;" : "=r"(hi) : "f"(af[mi][r]));
                    a_hi[mi][r] = hi;
                    a_lo[mi][r] = __float_as_uint(af[mi][r] - __uint_as_float(hi));
                }
            }
#pragma unroll
            for (int ni = 0; ni < 4; ni++) {
                const int nbase = (wn * 32 + ni * 8 + lr) * LDK;
                b[ni][0] = __float_as_uint(Bs[nbase + k0]);
                b[ni][1] = __float_as_uint(Bs[nbase + k0 + 4]);
            }
#pragma unroll
            for (int mi = 0; mi < 2; mi++)
#pragma unroll
                for (int ni = 0; ni < 4; ni++) {
                    asm volatile(
                        "mma.sync.aligned.m16n8k8.row.col.f32.tf32.tf32.f32 "
                        "{%0,%1,%2,%3}, {%4,%5,%6,%7}, {%8,%9}, {%0,%1,%2,%3};"
                        : "+f"(acc[mi][ni][0]), "+f"(acc[mi][ni][1]),
                          "+f"(acc[mi][ni][2]), "+f"(acc[mi][ni][3])
                        : "r"(a_lo[mi][0]), "r"(a_lo[mi][1]), "r"(a_lo[mi][2]), "r"(a_lo[mi][3]),
                          "r"(b[ni][0]), "r"(b[ni][1]));
                    asm volatile(
                        "mma.sync.aligned.m16n8k8.row.col.f32.tf32.tf32.f32 "
                        "{%0,%1,%2,%3}, {%4,%5,%6,%7}, {%8,%9}, {%0,%1,%2,%3};"
                        : "+f"(acc[mi][ni][0]), "+f"(acc[mi][ni][1]),
                          "+f"(acc[mi][ni][2]), "+f"(acc[mi][ni][3])
                        : "r"(a_hi[mi][0]), "r"(a_hi[mi][1]), "r"(a_hi[mi][2]), "r"(a_hi[mi][3]),
                          "r"(b[ni][0]), "r"(b[ni][1]));
                }
        }
        __syncthreads();
    }

    // epilogue: accumulators -> g_part
#pragma unroll
    for (int mi = 0; mi < 2; mi++)
#pragma unroll
        for (int h = 0; h < 2; h++) {
            const int m = m0 + wm * 32 + mi * 16 + h * 8 + lr;
            float* row = g_part + ((size_t)sp * A_ATOMS + m) * 64;
#pragma unroll
            for (int ni = 0; ni < 4; ni++) {
                const int col = wn * 32 + ni * 8 + lc * 2;
                *(float2*)(row + col) =
                    make_float2(acc[mi][ni][h * 2], acc[mi][ni][h * 2 + 1]);
            }
        }
}

// ---------------------------------------------------------------------------
// reduce split-K partials + BC (+ residual) + ReLU
// ---------------------------------------------------------------------------
__global__ __launch_bounds__(256) void epi_kernel(int bc_idx,
                                                  const float* __restrict__ resid,
                                                  int to_gh, float* __restrict__ out,
                                                  int add_res)
{
    int i = blockIdx.x * 256 + threadIdx.x;
    float s = 0.f;
#pragma unroll
    for (int sp = 0; sp < NSPLIT; sp++)
        s += g_part[(size_t)sp * MN + i];
    s += g_BC[(size_t)bc_idx * MN + i];
    if (add_res) s += resid[i];
    s = fmaxf(s, 0.f);
    (to_gh ? g_h : out)[i] = s;
}

// ---------------------------------------------------------------------------
extern "C" void kernel_launch(void* const* d_in, const int* in_sizes, int n_in,
                              void* d_out, int out_size)
{
    const float* x    = (const float*)d_in[0];
    const float* conn = (const float*)d_in[1];
    const float* bond = (const float*)d_in[2];
    const float* f0   = (const float*)d_in[3];
    const float* f1   = (const float*)d_in[4];
    float* out = (float*)d_out;

    cudaFuncSetAttribute(gemm_mma, cudaFuncAttributeMaxDynamicSharedMemorySize, SMEM_DYN);

    dim3 gg(A_ATOMS / BM, NSPLIT);

    bc_kernel<<<A_ATOMS, 64>>>(bond, f0, f1);

    // layer 0, conv 1: h = relu(conv(x, f0))
    w2_kernel<<<256, 256>>>(0, x, f0);
    gemm_mma<<<gg, 256, SMEM_DYN>>>(conn);
    epi_kernel<<<MN / 256, 256>>>(0, x, 1, out, 0);

    // layer 0, conv 2: out0 = relu(conv(h, f0) + x)
    w2_kernel<<<256, 256>>>(1, x, f0);
    gemm_mma<<<gg, 256, SMEM_DYN>>>(conn);
    epi_kernel<<<MN / 256, 256>>>(0, x, 1, out, 1);

    // layer 1, conv 1: h = relu(conv(out0, f1))
    w2_kernel<<<256, 256>>>(1, x, f1);
    gemm_mma<<<gg, 256, SMEM_DYN>>>(conn);
    epi_kernel<<<MN / 256, 256>>>(1, x, 1, out, 0);

    // layer 1, conv 2: final = relu(conv(h, f1) + x)
    w2_kernel<<<256, 256>>>(1, x, f1);
    gemm_mma<<<gg, 256, SMEM_DYN>>>(conn);
    epi_kernel<<<MN / 256, 256>>>(1, x, 0, out, 1);
}

// round 9
// speedup vs baseline: 1.3540x; 1.2464x over previous
#include <cuda_runtime.h>
#include <cstdint>
#include <cstddef>

// ---------------- problem constants ----------------
#define A_ATOMS 2048
#define DEPTH   64
#define FILT    12
#define KTOT    24576          // A_ATOMS * FILT
#define MN      131072         // A_ATOMS * DEPTH

// ---------------- GEMM config ----------------
#define BM      128
#define BN      64
#define BK      32             // floats of K per stage
#define NSPLIT  18
#define STAGES  4

#define LDK     36             // padded row length (floats) -> 144 B
#define A_STAGE_BYTES (BM * LDK * 4)        // 18432
#define B_STAGE_BYTES (BN * LDK * 4)        // 9216
#define STAGE_BYTES   (A_STAGE_BYTES + B_STAGE_BYTES)  // 27648
#define SMEM_DYN      (STAGES * STAGE_BYTES)           // 110592

// ---------------- static scratch ----------------
__device__ float g_Wt[64 * KTOT];       // W^T [o][k], RN tf32-rounded
__device__ float g_part[NSPLIT * MN];   // split-K partials
__device__ float g_h[MN];               // activation buffer
__device__ float g_BC[2 * MN];          // bond contributions

// ---------------------------------------------------------------------------
// BC[l][a][o] = sum_{f,j} bond[a,f,j] * filters_l[o,f,64+j]
// ---------------------------------------------------------------------------
__global__ __launch_bounds__(64) void bc_kernel(const float* __restrict__ bond,
                                                const float* __restrict__ f0,
                                                const float* __restrict__ f1)
{
    int a = blockIdx.x;
    int o = threadIdx.x;
    __shared__ float bs[24];
    if (o < 24) bs[o] = bond[a * 24 + o];
    __syncthreads();
    float acc0 = 0.f, acc1 = 0.f;
#pragma unroll
    for (int f = 0; f < FILT; f++)
#pragma unroll
        for (int j = 0; j < 2; j++) {
            float b = bs[f * 2 + j];
            acc0 += b * f0[o * 792 + f * 66 + 64 + j];
            acc1 += b * f1[o * 792 + f * 66 + 64 + j];
        }
    g_BC[a * 64 + o]      = acc0;
    g_BC[MN + a * 64 + o] = acc1;
}

// ---------------------------------------------------------------------------
// W^T[o][n*12+f] = round_rn_tf32( sum_d z[n,d] * filt[o,f,d] )
// ---------------------------------------------------------------------------
__global__ __launch_bounds__(256) void w2_kernel(int zsel,
                                                 const float* __restrict__ x,
                                                 const float* __restrict__ filt)
{
    const float* z = zsel ? g_h : x;
    __shared__ float act[8][64];
    __shared__ float fs[64][65];
    __shared__ float outp[64][96];
    const int n0  = blockIdx.x * 8;
    const int tid = threadIdx.x;

    if (tid < 128) {
        int r = tid >> 4, d = (tid & 15) * 4;
        *(float4*)&act[r][d] = *(const float4*)(z + (size_t)(n0 + r) * 64 + d);
    }

    const int ol = tid & 31;
    const int nl = tid >> 5;
    float acc[12][2];

#pragma unroll 1
    for (int f = 0; f < 12; f++) {
        __syncthreads();
        {
            int o  = tid >> 2;
            int d0 = (tid & 3) * 16;
#pragma unroll
            for (int c = 0; c < 8; c++) {
                float2 v = *(const float2*)(filt + (size_t)o * 792 + f * 66 + d0 + c * 2);
                fs[o][d0 + c * 2]     = v.x;
                fs[o][d0 + c * 2 + 1] = v.y;
            }
        }
        __syncthreads();
        float a0 = 0.f, a1 = 0.f;
#pragma unroll 16
        for (int d = 0; d < 64; d++) {
            float av = act[nl][d];
            a0 = fmaf(av, fs[ol * 2][d], a0);
            a1 = fmaf(av, fs[ol * 2 + 1][d], a1);
        }
        acc[f][0] = a0;
        acc[f][1] = a1;
    }

    __syncthreads();
#pragma unroll
    for (int f = 0; f < 12; f++) {
        outp[ol * 2][nl * 12 + f]     = acc[f][0];
        outp[ol * 2 + 1][nl * 12 + f] = acc[f][1];
    }
    __syncthreads();

#pragma unroll
    for (int t = 0; t < 24; t++) {
        int idx = tid + t * 256;
        int row = idx / 96, col = idx % 96;
        float v = outp[row][col];
        uint32_t u;
        asm("cvt.rna.tf32.f32 %0, %1;" : "=r"(u) : "f"(v));
        g_Wt[(size_t)row * KTOT + n0 * 12 + col] = __uint_as_float(u);
    }
}

// ---------------------------------------------------------------------------
// Big GEMM, mma.sync tf32 m16n8k8, single term; A is RNA-rounded to tf32
// in-register (unbiased), B pre-rounded in g_Wt:
//   part[sp][m][o] = sum_{k in split} conn[m][k] * Wt[o][k]
// grid (16 m-tiles, 18 k-splits), 256 threads (8 warps: 4M x 2N, 32x32 each),
// 4-stage cp.async pipeline, 2 CTAs/SM.
// ---------------------------------------------------------------------------
__global__ __launch_bounds__(256, 2) void gemm_mma(const float* __restrict__ Ag)
{
    extern __shared__ __align__(128) char smem[];

    const int tid  = threadIdx.x;
    const int wid  = tid >> 5;
    const int lane = tid & 31;
    const int wm   = wid & 3;
    const int wn   = wid >> 2;
    const int lr   = lane >> 2;
    const int lc   = lane & 3;

    const int sp   = blockIdx.y;
    const int kbeg = sp * 42 + (sp < 12 ? sp : 12);   // in BK units
    const int kcnt = 42 + (sp < 12 ? 1 : 0);
    const int m0   = blockIdx.x * BM;

    const float* Abase = Ag + (size_t)m0 * KTOT + (size_t)kbeg * BK;
    const float* Bbase = g_Wt + (size_t)kbeg * BK;

    const int a_row = tid >> 1;
    const int a_c0  = (tid & 1) * 4;
    const int b_row = tid >> 2;
    const int b_c0  = (tid & 3) * 2;

    auto load_stage = [&](int st, int j) {
        char* as = smem + st * STAGE_BYTES;
        char* bs = as + A_STAGE_BYTES;
        const char* ga = (const char*)(Abase + (size_t)a_row * KTOT + (size_t)j * BK);
        uint32_t da;
        asm("{ .reg .u64 t; cvta.to.shared.u64 t, %1; cvt.u32.u64 %0, t; }"
            : "=r"(da) : "l"(as + a_row * (LDK * 4)));
#pragma unroll
        for (int c = 0; c < 4; c++)
            asm volatile("cp.async.cg.shared.global [%0], [%1], 16;"
                         :: "r"(da + (a_c0 + c) * 16), "l"(ga + (a_c0 + c) * 16) : "memory");
        const char* gb = (const char*)(Bbase + (size_t)b_row * KTOT + (size_t)j * BK);
        uint32_t db;
        asm("{ .reg .u64 t; cvta.to.shared.u64 t, %1; cvt.u32.u64 %0, t; }"
            : "=r"(db) : "l"(bs + b_row * (LDK * 4)));
#pragma unroll
        for (int c = 0; c < 2; c++)
            asm volatile("cp.async.cg.shared.global [%0], [%1], 16;"
                         :: "r"(db + (b_c0 + c) * 16), "l"(gb + (b_c0 + c) * 16) : "memory");
        asm volatile("cp.async.commit_group;" ::: "memory");
    };

    float acc[2][4][4];
#pragma unroll
    for (int mi = 0; mi < 2; mi++)
#pragma unroll
        for (int ni = 0; ni < 4; ni++)
#pragma unroll
            for (int r = 0; r < 4; r++) acc[mi][ni][r] = 0.f;

    for (int j = 0; j < STAGES - 1; j++) load_stage(j, j);

    for (int i = 0; i < kcnt; i++) {
        const int s = i & (STAGES - 1);
        asm volatile("cp.async.wait_group %0;" :: "n"(STAGES - 2) : "memory");
        __syncthreads();

        const int j = i + STAGES - 1;
        if (j < kcnt) load_stage(j & (STAGES - 1), j);
        else asm volatile("cp.async.commit_group;" ::: "memory");

        const float* As = (const float*)(smem + s * STAGE_BYTES);
        const float* Bs = (const float*)(smem + s * STAGE_BYTES + A_STAGE_BYTES);

#pragma unroll
        for (int ks = 0; ks < 4; ks++) {
            const int k0 = ks * 8 + lc;
            uint32_t a[2][4], b[4][2];
#pragma unroll
            for (int mi = 0; mi < 2; mi++) {
                const int rbase = (wm * 32 + mi * 16 + lr) * LDK;
                float f0v = As[rbase + k0];
                float f1v = As[rbase + 8 * LDK + k0];
                float f2v = As[rbase + k0 + 4];
                float f3v = As[rbase + 8 * LDK + k0 + 4];
                // RNA round to tf32 in-register: unbiased A quantization
                asm("cvt.rna.tf32.f32 %0, %1;" : "=r"(a[mi][0]) : "f"(f0v));
                asm("cvt.rna.tf32.f32 %0, %1;" : "=r"(a[mi][1]) : "f"(f1v));
                asm("cvt.rna.tf32.f32 %0, %1;" : "=r"(a[mi][2]) : "f"(f2v));
                asm("cvt.rna.tf32.f32 %0, %1;" : "=r"(a[mi][3]) : "f"(f3v));
            }
#pragma unroll
            for (int ni = 0; ni < 4; ni++) {
                const int nbase = (wn * 32 + ni * 8 + lr) * LDK;
                b[ni][0] = __float_as_uint(Bs[nbase + k0]);
                b[ni][1] = __float_as_uint(Bs[nbase + k0 + 4]);
            }
#pragma unroll
            for (int mi = 0; mi < 2; mi++)
#pragma unroll
                for (int ni = 0; ni < 4; ni++)
                    asm volatile(
                        "mma.sync.aligned.m16n8k8.row.col.f32.tf32.tf32.f32 "
                        "{%0,%1,%2,%3}, {%4,%5,%6,%7}, {%8,%9}, {%0,%1,%2,%3};"
                        : "+f"(acc[mi][ni][0]), "+f"(acc[mi][ni][1]),
                          "+f"(acc[mi][ni][2]), "+f"(acc[mi][ni][3])
                        : "r"(a[mi][0]), "r"(a[mi][1]), "r"(a[mi][2]), "r"(a[mi][3]),
                          "r"(b[ni][0]), "r"(b[ni][1]));
        }
        __syncthreads();
    }

    // epilogue: accumulators -> g_part
#pragma unroll
    for (int mi = 0; mi < 2; mi++)
#pragma unroll
        for (int h = 0; h < 2; h++) {
            const int m = m0 + wm * 32 + mi * 16 + h * 8 + lr;
            float* row = g_part + ((size_t)sp * A_ATOMS + m) * 64;
#pragma unroll
            for (int ni = 0; ni < 4; ni++) {
                const int col = wn * 32 + ni * 8 + lc * 2;
                *(float2*)(row + col) =
                    make_float2(acc[mi][ni][h * 2], acc[mi][ni][h * 2 + 1]);
            }
        }
}

// ---------------------------------------------------------------------------
// reduce split-K partials + BC (+ residual) + ReLU
// ---------------------------------------------------------------------------
__global__ __launch_bounds__(256) void epi_kernel(int bc_idx,
                                                  const float* __restrict__ resid,
                                                  int to_gh, float* __restrict__ out,
                                                  int add_res)
{
    int i = blockIdx.x * 256 + threadIdx.x;
    float s = 0.f;
#pragma unroll
    for (int sp = 0; sp < NSPLIT; sp++)
        s += g_part[(size_t)sp * MN + i];
    s += g_BC[(size_t)bc_idx * MN + i];
    if (add_res) s += resid[i];
    s = fmaxf(s, 0.f);
    (to_gh ? g_h : out)[i] = s;
}

// ---------------------------------------------------------------------------
extern "C" void kernel_launch(void* const* d_in, const int* in_sizes, int n_in,
                              void* d_out, int out_size)
{
    const float* x    = (const float*)d_in[0];
    const float* conn = (const float*)d_in[1];
    const float* bond = (const float*)d_in[2];
    const float* f0   = (const float*)d_in[3];
    const float* f1   = (const float*)d_in[4];
    float* out = (float*)d_out;

    cudaFuncSetAttribute(gemm_mma, cudaFuncAttributeMaxDynamicSharedMemorySize, SMEM_DYN);

    dim3 gg(A_ATOMS / BM, NSPLIT);

    bc_kernel<<<A_ATOMS, 64>>>(bond, f0, f1);

    // layer 0, conv 1: h = relu(conv(x, f0))
    w2_kernel<<<256, 256>>>(0, x, f0);
    gemm_mma<<<gg, 256, SMEM_DYN>>>(conn);
    epi_kernel<<<MN / 256, 256>>>(0, x, 1, out, 0);

    // layer 0, conv 2: out0 = relu(conv(h, f0) + x)
    w2_kernel<<<256, 256>>>(1, x, f0);
    gemm_mma<<<gg, 256, SMEM_DYN>>>(conn);
    epi_kernel<<<MN / 256, 256>>>(0, x, 1, out, 1);

    // layer 1, conv 1: h = relu(conv(out0, f1))
    w2_kernel<<<256, 256>>>(1, x, f1);
    gemm_mma<<<gg, 256, SMEM_DYN>>>(conn);
    epi_kernel<<<MN / 256, 256>>>(1, x, 1, out, 0);

    // layer 1, conv 2: final = relu(conv(h, f1) + x)
    w2_kernel<<<256, 256>>>(1, x, f1);
    gemm_mma<<<gg, 256, SMEM_DYN>>>(conn);
    epi_kernel<<<MN / 256, 256>>>(1, x, 0, out, 1);
}